// round 1
// baseline (speedup 1.0000x reference)
#include <cuda_runtime.h>

#define B_    2
#define LQ_   2048
#define LK_   2048
#define DIM_  1024
#define HEADS_ 8
#define DH_   64
#define INNER_ 512

// ---------------- scratch (static device globals; no allocation) ----------------
__device__ float g_q [B_ * LQ_ * INNER_];
__device__ float g_k [B_ * LK_ * INNER_];
__device__ float g_v [B_ * LK_ * INNER_];
__device__ float g_ao[B_ * LQ_ * INNER_];

// ---------------- GEMM: C[M,N] = alpha * A[M,K] @ W[N,K]^T ----------------
// BM=BN=128, BK=16, 256 threads, 8x8 per thread.
__global__ __launch_bounds__(256)
void gemm_abT_kernel(const float* __restrict__ A, const float* __restrict__ W,
                     float* __restrict__ C, int M, int N, int K, float alpha)
{
    const int BM = 128, BN = 128, BK = 16;
    __shared__ float As[BK][BM + 4];
    __shared__ float Bs[BK][BN + 4];

    const int tid = threadIdx.x;
    const int tx = tid & 15;       // 0..15 -> N
    const int ty = tid >> 4;       // 0..15 -> M
    const int bm = blockIdx.y * BM;
    const int bn = blockIdx.x * BN;

    float acc[8][8];
#pragma unroll
    for (int i = 0; i < 8; i++)
#pragma unroll
        for (int j = 0; j < 8; j++) acc[i][j] = 0.0f;

    for (int k0 = 0; k0 < K; k0 += BK) {
        // load A tile (128x16) and W tile (128x16), 512 float4 each, 2 per thread
#pragma unroll
        for (int it = 0; it < 2; it++) {
            int idx = tid + it * 256;          // 0..511
            int m  = idx >> 2;
            int kq = idx & 3;
            float4 va = *(const float4*)&A[(size_t)(bm + m) * K + k0 + kq * 4];
            As[kq * 4 + 0][m] = va.x; As[kq * 4 + 1][m] = va.y;
            As[kq * 4 + 2][m] = va.z; As[kq * 4 + 3][m] = va.w;
            float4 vb = *(const float4*)&W[(size_t)(bn + m) * K + k0 + kq * 4];
            Bs[kq * 4 + 0][m] = vb.x; Bs[kq * 4 + 1][m] = vb.y;
            Bs[kq * 4 + 2][m] = vb.z; Bs[kq * 4 + 3][m] = vb.w;
        }
        __syncthreads();

#pragma unroll
        for (int kk = 0; kk < BK; kk++) {
            float ra[8], rb[8];
            float4 a0 = *(const float4*)&As[kk][ty * 8 + 0];
            float4 a1 = *(const float4*)&As[kk][ty * 8 + 4];
            ra[0]=a0.x; ra[1]=a0.y; ra[2]=a0.z; ra[3]=a0.w;
            ra[4]=a1.x; ra[5]=a1.y; ra[6]=a1.z; ra[7]=a1.w;
            float4 b0 = *(const float4*)&Bs[kk][tx * 8 + 0];
            float4 b1 = *(const float4*)&Bs[kk][tx * 8 + 4];
            rb[0]=b0.x; rb[1]=b0.y; rb[2]=b0.z; rb[3]=b0.w;
            rb[4]=b1.x; rb[5]=b1.y; rb[6]=b1.z; rb[7]=b1.w;
#pragma unroll
            for (int i = 0; i < 8; i++)
#pragma unroll
                for (int j = 0; j < 8; j++)
                    acc[i][j] += ra[i] * rb[j];
        }
        __syncthreads();
    }

#pragma unroll
    for (int i = 0; i < 8; i++) {
        int r = bm + ty * 8 + i;
#pragma unroll
        for (int j = 0; j < 8; j += 4) {
            float4 v = make_float4(acc[i][j] * alpha, acc[i][j+1] * alpha,
                                   acc[i][j+2] * alpha, acc[i][j+3] * alpha);
            *(float4*)&C[(size_t)r * N + bn + tx * 8 + j] = v;
        }
    }
}

// ---------------- fused masked flash attention ----------------
// block = (q-tile of 64 rows, head, batch); 256 threads, each owns 4x4 of S/O.
// smem: Qt (d-major 64x68), Kt (d-major 64x68), Vs (k-major 64x68),
//       Ms (mask tile 64x68, overwritten in place by P = exp(S-m)).
#define SROW 68
#define ATTN_SMEM (4 * 64 * SROW * (int)sizeof(float))

__global__ __launch_bounds__(256)
void attn_kernel(const float* __restrict__ q, const float* __restrict__ k,
                 const float* __restrict__ v, const float* __restrict__ mask,
                 float* __restrict__ out)
{
    extern __shared__ float smem[];
    float* Qt = smem;                 // Qt[d*SROW + r]
    float* Kt = Qt + 64 * SROW;       // Kt[d*SROW + c]
    float* Vs = Kt + 64 * SROW;       // Vs[c*SROW + d]
    float* Ms = Vs + 64 * SROW;       // Ms[r*SROW + c]  (mask, then P)

    const int tid = threadIdx.x;
    const int tx = tid & 15;          // -> key cols / d cols (x4)
    const int ty = tid >> 4;          // -> q rows (x4)
    const int qti = blockIdx.x, h = blockIdx.y, b = blockIdx.z;
    const int qbase = qti * 64;
    const size_t qoff = ((size_t)b * LQ_ + qbase) * INNER_ + h * DH_;

    // load Q tile, transposed to d-major
#pragma unroll
    for (int it = 0; it < 4; it++) {
        int idx = tid + it * 256;     // 0..1023
        int r = idx >> 4, dq = idx & 15;
        float4 vq = *(const float4*)&q[qoff + (size_t)r * INNER_ + dq * 4];
        Qt[(dq * 4 + 0) * SROW + r] = vq.x;
        Qt[(dq * 4 + 1) * SROW + r] = vq.y;
        Qt[(dq * 4 + 2) * SROW + r] = vq.z;
        Qt[(dq * 4 + 3) * SROW + r] = vq.w;
    }

    float m_i[4], l_i[4], o[4][4];
#pragma unroll
    for (int i = 0; i < 4; i++) {
        m_i[i] = -1e30f; l_i[i] = 0.0f;
#pragma unroll
        for (int j = 0; j < 4; j++) o[i][j] = 0.0f;
    }

    for (int kt = 0; kt < LK_ / 64; kt++) {
        const int kbase = kt * 64;
        const size_t koff = ((size_t)b * LK_ + kbase) * INNER_ + h * DH_;
#pragma unroll
        for (int it = 0; it < 4; it++) {
            int idx = tid + it * 256;
            int r = idx >> 4, dq = idx & 15;
            float4 vk = *(const float4*)&k[koff + (size_t)r * INNER_ + dq * 4];
            Kt[(dq * 4 + 0) * SROW + r] = vk.x;
            Kt[(dq * 4 + 1) * SROW + r] = vk.y;
            Kt[(dq * 4 + 2) * SROW + r] = vk.z;
            Kt[(dq * 4 + 3) * SROW + r] = vk.w;
            *(float4*)&Vs[r * SROW + dq * 4] =
                *(const float4*)&v[koff + (size_t)r * INNER_ + dq * 4];
            *(float4*)&Ms[r * SROW + dq * 4] =
                *(const float4*)&mask[((size_t)b * LQ_ + qbase + r) * LK_ + kbase + dq * 4];
        }
        __syncthreads();

        // S = Q K^T (scale was folded into Q projection)
        float s[4][4];
#pragma unroll
        for (int i = 0; i < 4; i++)
#pragma unroll
            for (int j = 0; j < 4; j++) s[i][j] = 0.0f;

#pragma unroll 8
        for (int d = 0; d < 64; d++) {
            float4 qv = *(const float4*)&Qt[d * SROW + ty * 4];
            float4 kv = *(const float4*)&Kt[d * SROW + tx * 4];
            s[0][0] += qv.x * kv.x; s[0][1] += qv.x * kv.y; s[0][2] += qv.x * kv.z; s[0][3] += qv.x * kv.w;
            s[1][0] += qv.y * kv.x; s[1][1] += qv.y * kv.y; s[1][2] += qv.y * kv.z; s[1][3] += qv.y * kv.w;
            s[2][0] += qv.z * kv.x; s[2][1] += qv.z * kv.y; s[2][2] += qv.z * kv.z; s[2][3] += qv.z * kv.w;
            s[3][0] += qv.w * kv.x; s[3][1] += qv.w * kv.y; s[3][2] += qv.w * kv.z; s[3][3] += qv.w * kv.w;
        }

        // additive mask + online softmax
#pragma unroll
        for (int i = 0; i < 4; i++) {
            float4 mv = *(const float4*)&Ms[(ty * 4 + i) * SROW + tx * 4];
            s[i][0] -= mv.x * 1e9f; s[i][1] -= mv.y * 1e9f;
            s[i][2] -= mv.z * 1e9f; s[i][3] -= mv.w * 1e9f;

            float rm = fmaxf(fmaxf(s[i][0], s[i][1]), fmaxf(s[i][2], s[i][3]));
#pragma unroll
            for (int off = 1; off < 16; off <<= 1)
                rm = fmaxf(rm, __shfl_xor_sync(0xffffffffu, rm, off));
            float mn = fmaxf(m_i[i], rm);
            float sc = __expf(m_i[i] - mn);
            m_i[i] = mn;
            float rs = 0.0f;
#pragma unroll
            for (int j = 0; j < 4; j++) {
                float p = __expf(s[i][j] - mn);
                s[i][j] = p; rs += p;
            }
#pragma unroll
            for (int off = 1; off < 16; off <<= 1)
                rs += __shfl_xor_sync(0xffffffffu, rs, off);
            l_i[i] = l_i[i] * sc + rs;
#pragma unroll
            for (int j = 0; j < 4; j++) o[i][j] *= sc;
        }

        // write P in place of the mask tile (per-thread-exclusive elements)
#pragma unroll
        for (int i = 0; i < 4; i++)
            *(float4*)&Ms[(ty * 4 + i) * SROW + tx * 4] =
                make_float4(s[i][0], s[i][1], s[i][2], s[i][3]);
        __syncthreads();

        // O += P @ V
#pragma unroll 4
        for (int k4 = 0; k4 < 16; k4++) {
            float pr[4][4];
#pragma unroll
            for (int i = 0; i < 4; i++) {
                float4 t = *(const float4*)&Ms[(ty * 4 + i) * SROW + k4 * 4];
                pr[i][0] = t.x; pr[i][1] = t.y; pr[i][2] = t.z; pr[i][3] = t.w;
            }
#pragma unroll
            for (int u = 0; u < 4; u++) {
                float4 vv = *(const float4*)&Vs[(k4 * 4 + u) * SROW + tx * 4];
#pragma unroll
                for (int i = 0; i < 4; i++) {
                    o[i][0] += pr[i][u] * vv.x;
                    o[i][1] += pr[i][u] * vv.y;
                    o[i][2] += pr[i][u] * vv.z;
                    o[i][3] += pr[i][u] * vv.w;
                }
            }
        }
        __syncthreads();
    }

    // epilogue: normalize and store
#pragma unroll
    for (int i = 0; i < 4; i++) {
        float inv = 1.0f / l_i[i];
        *(float4*)&out[qoff + (size_t)(ty * 4 + i) * INNER_ + tx * 4] =
            make_float4(o[i][0] * inv, o[i][1] * inv, o[i][2] * inv, o[i][3] * inv);
    }
}

// ---------------- launch ----------------
extern "C" void kernel_launch(void* const* d_in, const int* in_sizes, int n_in,
                              void* d_out, int out_size)
{
    (void)in_sizes; (void)n_in; (void)out_size;
    const float* x    = (const float*)d_in[0];
    const float* y    = (const float*)d_in[1];
    const float* mask = (const float*)d_in[2];
    const float* Wq   = (const float*)d_in[3];
    const float* Wk   = (const float*)d_in[4];
    const float* Wv   = (const float*)d_in[5];
    const float* Wo   = (const float*)d_in[6];
    float* out = (float*)d_out;

    float *q, *k, *v, *ao;
    cudaGetSymbolAddress((void**)&q,  g_q);
    cudaGetSymbolAddress((void**)&k,  g_k);
    cudaGetSymbolAddress((void**)&v,  g_v);
    cudaGetSymbolAddress((void**)&ao, g_ao);

    // projections: [B*L, DIM] @ [INNER, DIM]^T
    dim3 gP(INNER_ / 128, (B_ * LQ_) / 128);
    gemm_abT_kernel<<<gP, 256>>>(x, Wq, q, B_ * LQ_, INNER_, DIM_, 0.125f); // scale folded
    gemm_abT_kernel<<<gP, 256>>>(y, Wk, k, B_ * LK_, INNER_, DIM_, 1.0f);
    gemm_abT_kernel<<<gP, 256>>>(y, Wv, v, B_ * LK_, INNER_, DIM_, 1.0f);

    // fused masked attention
    cudaFuncSetAttribute(attn_kernel, cudaFuncAttributeMaxDynamicSharedMemorySize, ATTN_SMEM);
    attn_kernel<<<dim3(LQ_ / 64, HEADS_, B_), 256, ATTN_SMEM>>>(q, k, v, mask, ao);

    // output projection: [B*LQ, INNER] @ [DIM, INNER]^T -> d_out
    gemm_abT_kernel<<<dim3(DIM_ / 128, (B_ * LQ_) / 128), 256>>>(ao, Wo, out, B_ * LQ_, DIM_, INNER_, 1.0f);
}

// round 3
// speedup vs baseline: 3.5127x; 3.5127x over previous
#include <cuda_runtime.h>
#include <cuda_bf16.h>
#include <cstring>
#include <cstdint>

#define B_    2
#define LQ_   2048
#define LK_   2048
#define DIM_  1024
#define HEADS_ 8
#define DH_   64
#define INNER_ 512

// ---------------- scratch (static device globals; no allocation) ----------------
__device__ float g_q [B_ * LQ_ * INNER_];
__device__ float g_k [B_ * LK_ * INNER_];
__device__ float g_v [B_ * LK_ * INNER_];
__device__ float g_ao[B_ * LQ_ * INNER_];

// ---------------- helpers ----------------
__device__ __forceinline__ uint32_t pack2(float x, float y) {
    __nv_bfloat162 t = __floats2bfloat162_rn(x, y);
    uint32_t r;
    memcpy(&r, &t, 4);
    return r;
}
__device__ __forceinline__ uint32_t pack2lo(float x, float y, uint32_t hi) {
    __nv_bfloat162 h;
    memcpy(&h, &hi, 4);
    return pack2(x - __low2float(h), y - __high2float(h));
}

// D += A*B ; m16n8k16 bf16, fp32 accumulate
__device__ __forceinline__ void mma16816(float* c, const uint32_t* a,
                                         uint32_t b0, uint32_t b1) {
    asm volatile(
        "mma.sync.aligned.m16n8k16.row.col.f32.bf16.bf16.f32 "
        "{%0,%1,%2,%3}, {%4,%5,%6,%7}, {%8,%9}, {%0,%1,%2,%3};"
        : "+f"(c[0]), "+f"(c[1]), "+f"(c[2]), "+f"(c[3])
        : "r"(a[0]), "r"(a[1]), "r"(a[2]), "r"(a[3]), "r"(b0), "r"(b1));
}

// ---------------- tensor-core GEMM: C[M,N] = alpha * A[M,K] @ W[N,K]^T ----------
// Block tile 128x64, BK=32. 8 warps (4m x 2n), warp tile 32x32.
// Split-bf16: each fp32 operand = hi + lo bf16; 3 MMAs per logical mma.
// smem row stride = 20 words (32 data bf16 + 8 pad) -> conflict-free frag loads.
__global__ __launch_bounds__(256)
void gemm_tc_kernel(const float* __restrict__ A, const float* __restrict__ W,
                    float* __restrict__ C, int M, int N, int K, float alpha)
{
    __shared__ __align__(16) uint32_t Ah[128 * 20], Al[128 * 20];
    __shared__ __align__(16) uint32_t Bh[64 * 20],  Bl[64 * 20];

    const int tid = threadIdx.x;
    const int lane = tid & 31, warp = tid >> 5;
    const int wm = warp & 3, wn = warp >> 2;       // 4 x 2 warp grid
    const int g = lane >> 2, t = lane & 3;
    const int bm = blockIdx.y * 128, bn = blockIdx.x * 64;

    float c[2][4][4];
#pragma unroll
    for (int mt = 0; mt < 2; mt++)
#pragma unroll
        for (int nt = 0; nt < 4; nt++)
#pragma unroll
            for (int j = 0; j < 4; j++) c[mt][nt][j] = 0.0f;

    float4 pa[4], pb[2];

    // ---- prefetch first tile ----
#pragma unroll
    for (int i = 0; i < 4; i++) {
        int idx = tid + i * 256, m = idx >> 3, q = idx & 7;
        pa[i] = *(const float4*)&A[(size_t)(bm + m) * K + q * 4];
    }
#pragma unroll
    for (int i = 0; i < 2; i++) {
        int idx = tid + i * 256, m = idx >> 3, q = idx & 7;
        pb[i] = *(const float4*)&W[(size_t)(bn + m) * K + q * 4];
    }

    for (int k0 = 32;; k0 += 32) {
        // store prefetched tile to smem (split hi/lo)
#pragma unroll
        for (int i = 0; i < 4; i++) {
            int idx = tid + i * 256, m = idx >> 3, q = idx & 7;
            uint32_t h0 = pack2(pa[i].x, pa[i].y), h1 = pack2(pa[i].z, pa[i].w);
            Ah[m * 20 + q * 2] = h0;  Ah[m * 20 + q * 2 + 1] = h1;
            Al[m * 20 + q * 2] = pack2lo(pa[i].x, pa[i].y, h0);
            Al[m * 20 + q * 2 + 1] = pack2lo(pa[i].z, pa[i].w, h1);
        }
#pragma unroll
        for (int i = 0; i < 2; i++) {
            int idx = tid + i * 256, m = idx >> 3, q = idx & 7;
            uint32_t h0 = pack2(pb[i].x, pb[i].y), h1 = pack2(pb[i].z, pb[i].w);
            Bh[m * 20 + q * 2] = h0;  Bh[m * 20 + q * 2 + 1] = h1;
            Bl[m * 20 + q * 2] = pack2lo(pb[i].x, pb[i].y, h0);
            Bl[m * 20 + q * 2 + 1] = pack2lo(pb[i].z, pb[i].w, h1);
        }
        __syncthreads();

        const bool last = (k0 >= K);
        if (!last) {
#pragma unroll
            for (int i = 0; i < 4; i++) {
                int idx = tid + i * 256, m = idx >> 3, q = idx & 7;
                pa[i] = *(const float4*)&A[(size_t)(bm + m) * K + k0 + q * 4];
            }
#pragma unroll
            for (int i = 0; i < 2; i++) {
                int idx = tid + i * 256, m = idx >> 3, q = idx & 7;
                pb[i] = *(const float4*)&W[(size_t)(bn + m) * K + k0 + q * 4];
            }
        }

        // compute on smem tile: 2 k16 steps
#pragma unroll
        for (int s = 0; s < 2; s++) {
            uint32_t ah[2][4], al[2][4];
#pragma unroll
            for (int mt = 0; mt < 2; mt++) {
                int base = (wm * 32 + mt * 16 + g) * 20 + s * 8 + t;
                ah[mt][0] = Ah[base];       ah[mt][1] = Ah[base + 160];
                ah[mt][2] = Ah[base + 4];   ah[mt][3] = Ah[base + 164];
                al[mt][0] = Al[base];       al[mt][1] = Al[base + 160];
                al[mt][2] = Al[base + 4];   al[mt][3] = Al[base + 164];
            }
#pragma unroll
            for (int nt = 0; nt < 4; nt++) {
                int nb = (wn * 32 + nt * 8 + g) * 20 + s * 8 + t;
                uint32_t bh0 = Bh[nb], bh1 = Bh[nb + 4];
                uint32_t bl0 = Bl[nb], bl1 = Bl[nb + 4];
#pragma unroll
                for (int mt = 0; mt < 2; mt++) {
                    mma16816(c[mt][nt], ah[mt], bh0, bh1);
                    mma16816(c[mt][nt], ah[mt], bl0, bl1);
                    mma16816(c[mt][nt], al[mt], bh0, bh1);
                }
            }
        }
        if (last) break;
        __syncthreads();
    }

    // epilogue
#pragma unroll
    for (int mt = 0; mt < 2; mt++) {
        int row = bm + wm * 32 + mt * 16 + g;
#pragma unroll
        for (int nt = 0; nt < 4; nt++) {
            int col = bn + wn * 32 + nt * 8 + 2 * t;
            float2 v0 = make_float2(c[mt][nt][0] * alpha, c[mt][nt][1] * alpha);
            float2 v1 = make_float2(c[mt][nt][2] * alpha, c[mt][nt][3] * alpha);
            *(float2*)&C[(size_t)row * N + col] = v0;
            *(float2*)&C[(size_t)(row + 8) * N + col] = v1;
        }
    }
}

// ---------------- tensor-core fused masked flash attention ----------------
// Block: 128 q-rows x (head, batch). 8 warps; warp w owns q rows [16w,16w+16).
// Warp tile: m16 x n64 (full key tile) -> softmax is warp-local.
// Q fragments: loaded once from global, resident in registers.
// P: stays in registers (C-frag cols == A-frag k-pairs), split to bf16 on the fly.
// K smem: [key][d] d-contiguous; V smem: transposed [d][key] key-contiguous.
// Row stride 36 words (64 data bf16 + 8 pad) -> conflict-free frag loads.
__global__ __launch_bounds__(256)
void attn_tc_kernel(const float* __restrict__ q, const float* __restrict__ k,
                    const float* __restrict__ v, const float* __restrict__ mask,
                    float* __restrict__ out)
{
    __shared__ __align__(16) uint32_t Kh[64 * 36], Kl[64 * 36];
    __shared__ __align__(16) uint32_t Vh[64 * 36], Vl[64 * 36];

    const int tid = threadIdx.x;
    const int lane = tid & 31, warp = tid >> 5;
    const int g = lane >> 2, t = lane & 3;
    const int qti = blockIdx.x, h = blockIdx.y, b = blockIdx.z;
    const int qbase = qti * 128;
    const size_t qoff = ((size_t)b * LQ_ + qbase) * INNER_ + h * DH_;
    const int qrow = warp * 16 + g;      // local q row (and +8)

    // ---- Q fragments (hi/lo), resident ----
    uint32_t qh[4][4], ql[4][4];
    {
        const float* qp = q + qoff + (size_t)qrow * INNER_;
#pragma unroll
        for (int s = 0; s < 4; s++) {
            float2 x0 = *(const float2*)&qp[s * 16 + 2 * t];
            float2 x1 = *(const float2*)&qp[8 * INNER_ + s * 16 + 2 * t];
            float2 x2 = *(const float2*)&qp[s * 16 + 8 + 2 * t];
            float2 x3 = *(const float2*)&qp[8 * INNER_ + s * 16 + 8 + 2 * t];
            qh[s][0] = pack2(x0.x, x0.y);  ql[s][0] = pack2lo(x0.x, x0.y, qh[s][0]);
            qh[s][1] = pack2(x1.x, x1.y);  ql[s][1] = pack2lo(x1.x, x1.y, qh[s][1]);
            qh[s][2] = pack2(x2.x, x2.y);  ql[s][2] = pack2lo(x2.x, x2.y, qh[s][2]);
            qh[s][3] = pack2(x3.x, x3.y);  ql[s][3] = pack2lo(x3.x, x3.y, qh[s][3]);
        }
    }

    float m0 = -1e30f, m1 = -1e30f, l0 = 0.0f, l1 = 0.0f;
    float o[8][4];
#pragma unroll
    for (int nd = 0; nd < 8; nd++)
#pragma unroll
        for (int j = 0; j < 4; j++) o[nd][j] = 0.0f;

    __nv_bfloat16* Vh16 = (__nv_bfloat16*)Vh;
    __nv_bfloat16* Vl16 = (__nv_bfloat16*)Vl;

    for (int kt = 0; kt < LK_ / 64; kt++) {
        __syncthreads();   // previous iteration's smem reads done
        const size_t koff = ((size_t)b * LK_ + kt * 64) * INNER_ + h * DH_;
#pragma unroll
        for (int i = 0; i < 4; i++) {
            int idx = tid + i * 256, r = idx >> 4, q4 = idx & 15;
            float4 kv = *(const float4*)&k[koff + (size_t)r * INNER_ + q4 * 4];
            uint32_t h0 = pack2(kv.x, kv.y), h1 = pack2(kv.z, kv.w);
            Kh[r * 36 + q4 * 2] = h0;  Kh[r * 36 + q4 * 2 + 1] = h1;
            Kl[r * 36 + q4 * 2] = pack2lo(kv.x, kv.y, h0);
            Kl[r * 36 + q4 * 2 + 1] = pack2lo(kv.z, kv.w, h1);

            float4 vv = *(const float4*)&v[koff + (size_t)r * INNER_ + q4 * 4];
            float vf[4] = {vv.x, vv.y, vv.z, vv.w};
#pragma unroll
            for (int j = 0; j < 4; j++) {
                __nv_bfloat16 hi = __float2bfloat16(vf[j]);
                Vh16[(q4 * 4 + j) * 72 + r] = hi;
                Vl16[(q4 * 4 + j) * 72 + r] =
                    __float2bfloat16(vf[j] - __bfloat162float(hi));
            }
        }
        __syncthreads();

        // ---- S = Q K^T (scale folded into Q projection) ----
        float s[8][4];
#pragma unroll
        for (int nt = 0; nt < 8; nt++)
#pragma unroll
            for (int j = 0; j < 4; j++) s[nt][j] = 0.0f;

#pragma unroll
        for (int nt = 0; nt < 8; nt++) {
#pragma unroll
            for (int s16 = 0; s16 < 4; s16++) {
                int nb = (nt * 8 + g) * 36 + s16 * 8 + t;
                uint32_t bh0 = Kh[nb], bh1 = Kh[nb + 4];
                uint32_t bl0 = Kl[nb], bl1 = Kl[nb + 4];
                mma16816(s[nt], qh[s16], bh0, bh1);
                mma16816(s[nt], qh[s16], bl0, bl1);
                mma16816(s[nt], ql[s16], bh0, bh1);
            }
        }

        // ---- additive mask (read straight into fragment positions) ----
        {
            const float* mrow0 = mask + ((size_t)b * LQ_ + qbase + qrow) * LK_ + kt * 64;
            const float* mrow1 = mrow0 + 8 * (size_t)LK_;
#pragma unroll
            for (int nt = 0; nt < 8; nt++) {
                float2 ma = *(const float2*)&mrow0[nt * 8 + 2 * t];
                float2 mb = *(const float2*)&mrow1[nt * 8 + 2 * t];
                s[nt][0] -= ma.x * 1e9f;  s[nt][1] -= ma.y * 1e9f;
                s[nt][2] -= mb.x * 1e9f;  s[nt][3] -= mb.y * 1e9f;
            }
        }

        // ---- online softmax (warp-local; rows g and g+8) ----
        float rm0 = -1e30f, rm1 = -1e30f;
#pragma unroll
        for (int nt = 0; nt < 8; nt++) {
            rm0 = fmaxf(rm0, fmaxf(s[nt][0], s[nt][1]));
            rm1 = fmaxf(rm1, fmaxf(s[nt][2], s[nt][3]));
        }
#pragma unroll
        for (int off = 1; off < 4; off <<= 1) {
            rm0 = fmaxf(rm0, __shfl_xor_sync(0xffffffffu, rm0, off));
            rm1 = fmaxf(rm1, __shfl_xor_sync(0xffffffffu, rm1, off));
        }
        float nm0 = fmaxf(m0, rm0), nm1 = fmaxf(m1, rm1);
        float sc0 = __expf(m0 - nm0), sc1 = __expf(m1 - nm1);
        m0 = nm0; m1 = nm1;

        float rs0 = 0.0f, rs1 = 0.0f;
#pragma unroll
        for (int nt = 0; nt < 8; nt++) {
            s[nt][0] = __expf(s[nt][0] - m0);  rs0 += s[nt][0];
            s[nt][1] = __expf(s[nt][1] - m0);  rs0 += s[nt][1];
            s[nt][2] = __expf(s[nt][2] - m1);  rs1 += s[nt][2];
            s[nt][3] = __expf(s[nt][3] - m1);  rs1 += s[nt][3];
        }
#pragma unroll
        for (int off = 1; off < 4; off <<= 1) {
            rs0 += __shfl_xor_sync(0xffffffffu, rs0, off);
            rs1 += __shfl_xor_sync(0xffffffffu, rs1, off);
        }
        l0 = l0 * sc0 + rs0;
        l1 = l1 * sc1 + rs1;
#pragma unroll
        for (int nd = 0; nd < 8; nd++) {
            o[nd][0] *= sc0;  o[nd][1] *= sc0;
            o[nd][2] *= sc1;  o[nd][3] *= sc1;
        }

        // ---- O += P @ V (P re-packed from S fragments, no smem round-trip) ----
#pragma unroll
        for (int kk = 0; kk < 4; kk++) {
            uint32_t ph[4], pl[4];
            ph[0] = pack2(s[2 * kk][0], s[2 * kk][1]);
            ph[1] = pack2(s[2 * kk][2], s[2 * kk][3]);
            ph[2] = pack2(s[2 * kk + 1][0], s[2 * kk + 1][1]);
            ph[3] = pack2(s[2 * kk + 1][2], s[2 * kk + 1][3]);
            pl[0] = pack2lo(s[2 * kk][0], s[2 * kk][1], ph[0]);
            pl[1] = pack2lo(s[2 * kk][2], s[2 * kk][3], ph[1]);
            pl[2] = pack2lo(s[2 * kk + 1][0], s[2 * kk + 1][1], ph[2]);
            pl[3] = pack2lo(s[2 * kk + 1][2], s[2 * kk + 1][3], ph[3]);
#pragma unroll
            for (int nd = 0; nd < 8; nd++) {
                int nb = (nd * 8 + g) * 36 + kk * 8 + t;
                uint32_t bh0 = Vh[nb], bh1 = Vh[nb + 4];
                uint32_t bl0 = Vl[nb], bl1 = Vl[nb + 4];
                mma16816(o[nd], ph, bh0, bh1);
                mma16816(o[nd], ph, bl0, bl1);
                mma16816(o[nd], pl, bh0, bh1);
            }
        }
    }

    // ---- epilogue ----
    float inv0 = 1.0f / l0, inv1 = 1.0f / l1;
    float* op = out + qoff + (size_t)qrow * INNER_;
#pragma unroll
    for (int nd = 0; nd < 8; nd++) {
        *(float2*)&op[nd * 8 + 2 * t] =
            make_float2(o[nd][0] * inv0, o[nd][1] * inv0);
        *(float2*)&op[8 * INNER_ + nd * 8 + 2 * t] =
            make_float2(o[nd][2] * inv1, o[nd][3] * inv1);
    }
}

// ---------------- launch ----------------
extern "C" void kernel_launch(void* const* d_in, const int* in_sizes, int n_in,
                              void* d_out, int out_size)
{
    (void)in_sizes; (void)n_in; (void)out_size;
    const float* x    = (const float*)d_in[0];
    const float* y    = (const float*)d_in[1];
    const float* mask = (const float*)d_in[2];
    const float* Wq   = (const float*)d_in[3];
    const float* Wk   = (const float*)d_in[4];
    const float* Wv   = (const float*)d_in[5];
    const float* Wo   = (const float*)d_in[6];
    float* out = (float*)d_out;

    float *q, *k, *v, *ao;
    cudaGetSymbolAddress((void**)&q,  g_q);
    cudaGetSymbolAddress((void**)&k,  g_k);
    cudaGetSymbolAddress((void**)&v,  g_v);
    cudaGetSymbolAddress((void**)&ao, g_ao);

    // projections: [B*L, DIM] @ [INNER, DIM]^T
    dim3 gP(INNER_ / 64, (B_ * LQ_) / 128);
    gemm_tc_kernel<<<gP, 256>>>(x, Wq, q, B_ * LQ_, INNER_, DIM_, 0.125f);
    gemm_tc_kernel<<<gP, 256>>>(y, Wk, k, B_ * LK_, INNER_, DIM_, 1.0f);
    gemm_tc_kernel<<<gP, 256>>>(y, Wv, v, B_ * LK_, INNER_, DIM_, 1.0f);

    // fused masked attention
    attn_tc_kernel<<<dim3(LQ_ / 128, HEADS_, B_), 256>>>(q, k, v, mask, ao);

    // output projection: [B*LQ, INNER] @ [DIM, INNER]^T -> d_out
    gemm_tc_kernel<<<dim3(DIM_ / 64, (B_ * LQ_) / 128), 256>>>(
        ao, Wo, out, B_ * LQ_, DIM_, INNER_, 1.0f);
}

// round 4
// speedup vs baseline: 4.2720x; 1.2162x over previous
#include <cuda_runtime.h>
#include <cuda_bf16.h>
#include <cstring>
#include <cstdint>

#define B_    2
#define LQ_   2048
#define LK_   2048
#define DIM_  1024
#define HEADS_ 8
#define DH_   64
#define INNER_ 512

// ---------------- scratch (static device globals; no allocation) ----------------
__device__ float g_q [B_ * LQ_ * INNER_];
__device__ float g_k [B_ * LK_ * INNER_];
__device__ float g_v [B_ * LK_ * INNER_];
__device__ float g_ao[B_ * LQ_ * INNER_];

// ---------------- helpers ----------------
__device__ __forceinline__ uint32_t pack2(float x, float y) {
    __nv_bfloat162 t = __floats2bfloat162_rn(x, y);
    uint32_t r;
    memcpy(&r, &t, 4);
    return r;
}
__device__ __forceinline__ uint32_t pack2lo(float x, float y, uint32_t hi) {
    __nv_bfloat162 h;
    memcpy(&h, &hi, 4);
    return pack2(x - __low2float(h), y - __high2float(h));
}

// D += A*B ; m16n8k16 bf16, fp32 accumulate
__device__ __forceinline__ void mma16816(float* c, const uint32_t* a,
                                         uint32_t b0, uint32_t b1) {
    asm volatile(
        "mma.sync.aligned.m16n8k16.row.col.f32.bf16.bf16.f32 "
        "{%0,%1,%2,%3}, {%4,%5,%6,%7}, {%8,%9}, {%0,%1,%2,%3};"
        : "+f"(c[0]), "+f"(c[1]), "+f"(c[2]), "+f"(c[3])
        : "r"(a[0]), "r"(a[1]), "r"(a[2]), "r"(a[3]), "r"(b0), "r"(b1));
}

__device__ __forceinline__ void ldsm4(uint32_t& r0, uint32_t& r1,
                                      uint32_t& r2, uint32_t& r3, uint32_t addr) {
    asm volatile("ldmatrix.sync.aligned.m8n8.x4.shared.b16 {%0,%1,%2,%3}, [%4];"
                 : "=r"(r0), "=r"(r1), "=r"(r2), "=r"(r3) : "r"(addr));
}
__device__ __forceinline__ void ldsm4t(uint32_t& r0, uint32_t& r1,
                                       uint32_t& r2, uint32_t& r3, uint32_t addr) {
    asm volatile("ldmatrix.sync.aligned.m8n8.x4.trans.shared.b16 {%0,%1,%2,%3}, [%4];"
                 : "=r"(r0), "=r"(r1), "=r"(r2), "=r"(r3) : "r"(addr));
}
__device__ __forceinline__ uint32_t sptr(const void* p) {
    return (uint32_t)__cvta_generic_to_shared(p);
}

// ---------------- tensor-core GEMM: C[M,N] = alpha * A[M,K] @ W[N,K]^T ----------
// Block tile 128x64, BK=32. 8 warps (4m x 2n), warp tile 32x32.
// Split-bf16 fp32 emulation (3 MMAs). ldmatrix fragment loads; MMAs issued in
// rounds of independent accumulators.
__global__ __launch_bounds__(256)
void gemm_tc_kernel(const float* __restrict__ A, const float* __restrict__ W,
                    float* __restrict__ C, int M, int N, int K, float alpha)
{
    __shared__ __align__(16) uint32_t Ah[128 * 20], Al[128 * 20];
    __shared__ __align__(16) uint32_t Bh[64 * 20],  Bl[64 * 20];

    const int tid = threadIdx.x;
    const int lane = tid & 31, warp = tid >> 5;
    const int wm = warp & 3, wn = warp >> 2;       // 4 x 2 warp grid
    const int g = lane >> 2, t = lane & 3;
    const int bm = blockIdx.y * 128, bn = blockIdx.x * 64;

    const uint32_t ahB = sptr(Ah), alB = sptr(Al), bhB = sptr(Bh), blB = sptr(Bl);

    float c[2][4][4];
#pragma unroll
    for (int mt = 0; mt < 2; mt++)
#pragma unroll
        for (int nt = 0; nt < 4; nt++)
#pragma unroll
            for (int j = 0; j < 4; j++) c[mt][nt][j] = 0.0f;

    float4 pa[4], pb[2];

    // ---- prefetch first tile ----
#pragma unroll
    for (int i = 0; i < 4; i++) {
        int idx = tid + i * 256, m = idx >> 3, q = idx & 7;
        pa[i] = *(const float4*)&A[(size_t)(bm + m) * K + q * 4];
    }
#pragma unroll
    for (int i = 0; i < 2; i++) {
        int idx = tid + i * 256, m = idx >> 3, q = idx & 7;
        pb[i] = *(const float4*)&W[(size_t)(bn + m) * K + q * 4];
    }

    for (int k0 = 32;; k0 += 32) {
        // store prefetched tile to smem (split hi/lo)
#pragma unroll
        for (int i = 0; i < 4; i++) {
            int idx = tid + i * 256, m = idx >> 3, q = idx & 7;
            uint32_t h0 = pack2(pa[i].x, pa[i].y), h1 = pack2(pa[i].z, pa[i].w);
            Ah[m * 20 + q * 2] = h0;  Ah[m * 20 + q * 2 + 1] = h1;
            Al[m * 20 + q * 2] = pack2lo(pa[i].x, pa[i].y, h0);
            Al[m * 20 + q * 2 + 1] = pack2lo(pa[i].z, pa[i].w, h1);
        }
#pragma unroll
        for (int i = 0; i < 2; i++) {
            int idx = tid + i * 256, m = idx >> 3, q = idx & 7;
            uint32_t h0 = pack2(pb[i].x, pb[i].y), h1 = pack2(pb[i].z, pb[i].w);
            Bh[m * 20 + q * 2] = h0;  Bh[m * 20 + q * 2 + 1] = h1;
            Bl[m * 20 + q * 2] = pack2lo(pb[i].x, pb[i].y, h0);
            Bl[m * 20 + q * 2 + 1] = pack2lo(pb[i].z, pb[i].w, h1);
        }
        __syncthreads();

        const bool last = (k0 >= K);
        if (!last) {
#pragma unroll
            for (int i = 0; i < 4; i++) {
                int idx = tid + i * 256, m = idx >> 3, q = idx & 7;
                pa[i] = *(const float4*)&A[(size_t)(bm + m) * K + k0 + q * 4];
            }
#pragma unroll
            for (int i = 0; i < 2; i++) {
                int idx = tid + i * 256, m = idx >> 3, q = idx & 7;
                pb[i] = *(const float4*)&W[(size_t)(bn + m) * K + k0 + q * 4];
            }
        }

        // compute on smem tile: 2 k16 steps
#pragma unroll
        for (int s = 0; s < 2; s++) {
            uint32_t ah[2][4], al[2][4];
#pragma unroll
            for (int mt = 0; mt < 2; mt++) {
                uint32_t row = wm * 32 + mt * 16 + (lane & 7) + ((lane >> 3) & 1) * 8;
                uint32_t off = (row * 20 + s * 8 + ((lane >> 4) & 1) * 4) * 4;
                ldsm4(ah[mt][0], ah[mt][1], ah[mt][2], ah[mt][3], ahB + off);
                ldsm4(al[mt][0], al[mt][1], al[mt][2], al[mt][3], alB + off);
            }
            uint32_t bh[4][2], bl[4][2];
#pragma unroll
            for (int p2 = 0; p2 < 2; p2++) {
                uint32_t row = wn * 32 + p2 * 16 + ((lane >> 4) & 1) * 8 + (lane & 7);
                uint32_t off = (row * 20 + s * 8 + ((lane >> 3) & 1) * 4) * 4;
                ldsm4(bh[2*p2][0], bh[2*p2][1], bh[2*p2+1][0], bh[2*p2+1][1], bhB + off);
                ldsm4(bl[2*p2][0], bl[2*p2][1], bl[2*p2+1][0], bl[2*p2+1][1], blB + off);
            }
            // rounds of 8 independent MMAs
#pragma unroll
            for (int nt = 0; nt < 4; nt++)
#pragma unroll
                for (int mt = 0; mt < 2; mt++)
                    mma16816(c[mt][nt], ah[mt], bh[nt][0], bh[nt][1]);
#pragma unroll
            for (int nt = 0; nt < 4; nt++)
#pragma unroll
                for (int mt = 0; mt < 2; mt++)
                    mma16816(c[mt][nt], ah[mt], bl[nt][0], bl[nt][1]);
#pragma unroll
            for (int nt = 0; nt < 4; nt++)
#pragma unroll
                for (int mt = 0; mt < 2; mt++)
                    mma16816(c[mt][nt], al[mt], bh[nt][0], bh[nt][1]);
        }
        if (last) break;
        __syncthreads();
    }

    // epilogue
#pragma unroll
    for (int mt = 0; mt < 2; mt++) {
        int row = bm + wm * 32 + mt * 16 + g;
#pragma unroll
        for (int nt = 0; nt < 4; nt++) {
            int col = bn + wn * 32 + nt * 8 + 2 * t;
            float2 v0 = make_float2(c[mt][nt][0] * alpha, c[mt][nt][1] * alpha);
            float2 v1 = make_float2(c[mt][nt][2] * alpha, c[mt][nt][3] * alpha);
            *(float2*)&C[(size_t)row * N + col] = v0;
            *(float2*)&C[(size_t)(row + 8) * N + col] = v1;
        }
    }
}

// ---------------- tensor-core fused masked flash attention ----------------
// Block: 128 q-rows x (head, batch). 8 warps; warp w owns q rows [16w,16w+16).
// K and V both stored row-major [key][d] hi/lo in smem (stride 36 words = 144B,
// odd multiple of 16B -> conflict-free ldmatrix). K frags via ldmatrix, V frags
// via ldmatrix.trans. Double-buffered tiles; one syncthreads per key tile.
#define SKW 36
#define TILE_W (64 * SKW)           // words per array
#define BUF_W  (4 * TILE_W)         // Kh,Kl,Vh,Vl
#define ATTN_SMEM_BYTES (2 * BUF_W * 4)

__global__ __launch_bounds__(256)
void attn_tc_kernel(const float* __restrict__ q, const float* __restrict__ k,
                    const float* __restrict__ v, const float* __restrict__ mask,
                    float* __restrict__ out)
{
    extern __shared__ __align__(16) uint32_t asm_[];

    const int tid = threadIdx.x;
    const int lane = tid & 31, warp = tid >> 5;
    const int g = lane >> 2, t = lane & 3;
    const int qti = blockIdx.x, h = blockIdx.y, b = blockIdx.z;
    const int qbase = qti * 128;
    const size_t qoff = ((size_t)b * LQ_ + qbase) * INNER_ + h * DH_;
    const int qrow = warp * 16 + g;      // local q row (and +8)

    // ---- Q fragments (hi/lo), resident ----
    uint32_t qh[4][4], ql[4][4];
    {
        const float* qp = q + qoff + (size_t)qrow * INNER_;
#pragma unroll
        for (int s = 0; s < 4; s++) {
            float2 x0 = *(const float2*)&qp[s * 16 + 2 * t];
            float2 x1 = *(const float2*)&qp[8 * INNER_ + s * 16 + 2 * t];
            float2 x2 = *(const float2*)&qp[s * 16 + 8 + 2 * t];
            float2 x3 = *(const float2*)&qp[8 * INNER_ + s * 16 + 8 + 2 * t];
            qh[s][0] = pack2(x0.x, x0.y);  ql[s][0] = pack2lo(x0.x, x0.y, qh[s][0]);
            qh[s][1] = pack2(x1.x, x1.y);  ql[s][1] = pack2lo(x1.x, x1.y, qh[s][1]);
            qh[s][2] = pack2(x2.x, x2.y);  ql[s][2] = pack2lo(x2.x, x2.y, qh[s][2]);
            qh[s][3] = pack2(x3.x, x3.y);  ql[s][3] = pack2lo(x3.x, x3.y, qh[s][3]);
        }
    }

    float m0 = -1e30f, m1 = -1e30f, l0 = 0.0f, l1 = 0.0f;
    float o[8][4];
#pragma unroll
    for (int nd = 0; nd < 8; nd++)
#pragma unroll
        for (int j = 0; j < 4; j++) o[nd][j] = 0.0f;

    const int NT = LK_ / 64;

    // ---- prologue: load tile 0 into buffer 0 ----
    {
        uint32_t* Kh = asm_;              uint32_t* Kl = Kh + TILE_W;
        uint32_t* Vh = Kl + TILE_W;       uint32_t* Vl = Vh + TILE_W;
        const size_t koff = ((size_t)b * LK_) * INNER_ + h * DH_;
#pragma unroll
        for (int i = 0; i < 4; i++) {
            int idx = tid + i * 256, r = idx >> 4, q4 = idx & 15;
            float4 kv = *(const float4*)&k[koff + (size_t)r * INNER_ + q4 * 4];
            float4 vv = *(const float4*)&v[koff + (size_t)r * INNER_ + q4 * 4];
            uint32_t h0 = pack2(kv.x, kv.y), h1 = pack2(kv.z, kv.w);
            Kh[r * SKW + q4 * 2] = h0;  Kh[r * SKW + q4 * 2 + 1] = h1;
            Kl[r * SKW + q4 * 2] = pack2lo(kv.x, kv.y, h0);
            Kl[r * SKW + q4 * 2 + 1] = pack2lo(kv.z, kv.w, h1);
            uint32_t w0 = pack2(vv.x, vv.y), w1 = pack2(vv.z, vv.w);
            Vh[r * SKW + q4 * 2] = w0;  Vh[r * SKW + q4 * 2 + 1] = w1;
            Vl[r * SKW + q4 * 2] = pack2lo(vv.x, vv.y, w0);
            Vl[r * SKW + q4 * 2 + 1] = pack2lo(vv.z, vv.w, w1);
        }
    }
    __syncthreads();

    float4 pk[4], pv[4];

    for (int kt = 0; kt < NT; kt++) {
        const int p = kt & 1;
        const uint32_t khB = sptr(asm_ + p * BUF_W);
        const uint32_t klB = khB + TILE_W * 4;
        const uint32_t vhB = klB + TILE_W * 4;
        const uint32_t vlB = vhB + TILE_W * 4;
        const bool more = (kt + 1 < NT);

        // ---- early global prefetch of next tile ----
        if (more) {
            const size_t koff = ((size_t)b * LK_ + (kt + 1) * 64) * INNER_ + h * DH_;
#pragma unroll
            for (int i = 0; i < 4; i++) {
                int idx = tid + i * 256, r = idx >> 4, q4 = idx & 15;
                pk[i] = *(const float4*)&k[koff + (size_t)r * INNER_ + q4 * 4];
                pv[i] = *(const float4*)&v[koff + (size_t)r * INNER_ + q4 * 4];
            }
        }

        // ---- S = Q K^T ----
        float s[8][4];
#pragma unroll
        for (int nt = 0; nt < 8; nt++)
#pragma unroll
            for (int j = 0; j < 4; j++) s[nt][j] = 0.0f;

#pragma unroll
        for (int s16 = 0; s16 < 4; s16++) {
#pragma unroll
            for (int half = 0; half < 2; half++) {
                uint32_t bh[4][2], bl[4][2];
#pragma unroll
                for (int pp = 0; pp < 2; pp++) {
                    int p2 = half * 2 + pp;
                    uint32_t row = p2 * 16 + ((lane >> 4) & 1) * 8 + (lane & 7);
                    uint32_t off = (row * SKW + s16 * 8 + ((lane >> 3) & 1) * 4) * 4;
                    ldsm4(bh[2*pp][0], bh[2*pp][1], bh[2*pp+1][0], bh[2*pp+1][1], khB + off);
                    ldsm4(bl[2*pp][0], bl[2*pp][1], bl[2*pp+1][0], bl[2*pp+1][1], klB + off);
                }
#pragma unroll
                for (int j = 0; j < 4; j++)
                    mma16816(s[half*4+j], qh[s16], bh[j][0], bh[j][1]);
#pragma unroll
                for (int j = 0; j < 4; j++)
                    mma16816(s[half*4+j], qh[s16], bl[j][0], bl[j][1]);
#pragma unroll
                for (int j = 0; j < 4; j++)
                    mma16816(s[half*4+j], ql[s16], bh[j][0], bh[j][1]);
            }
        }

        // ---- additive mask ----
        {
            const float* mrow0 = mask + ((size_t)b * LQ_ + qbase + qrow) * LK_ + kt * 64;
            const float* mrow1 = mrow0 + 8 * (size_t)LK_;
#pragma unroll
            for (int nt = 0; nt < 8; nt++) {
                float2 ma = *(const float2*)&mrow0[nt * 8 + 2 * t];
                float2 mb = *(const float2*)&mrow1[nt * 8 + 2 * t];
                s[nt][0] -= ma.x * 1e9f;  s[nt][1] -= ma.y * 1e9f;
                s[nt][2] -= mb.x * 1e9f;  s[nt][3] -= mb.y * 1e9f;
            }
        }

        // ---- online softmax (warp-local; rows g and g+8) ----
        float rm0 = -1e30f, rm1 = -1e30f;
#pragma unroll
        for (int nt = 0; nt < 8; nt++) {
            rm0 = fmaxf(rm0, fmaxf(s[nt][0], s[nt][1]));
            rm1 = fmaxf(rm1, fmaxf(s[nt][2], s[nt][3]));
        }
#pragma unroll
        for (int off = 1; off < 4; off <<= 1) {
            rm0 = fmaxf(rm0, __shfl_xor_sync(0xffffffffu, rm0, off));
            rm1 = fmaxf(rm1, __shfl_xor_sync(0xffffffffu, rm1, off));
        }
        float nm0 = fmaxf(m0, rm0), nm1 = fmaxf(m1, rm1);
        float sc0 = __expf(m0 - nm0), sc1 = __expf(m1 - nm1);
        m0 = nm0; m1 = nm1;

        float rs0 = 0.0f, rs1 = 0.0f;
#pragma unroll
        for (int nt = 0; nt < 8; nt++) {
            s[nt][0] = __expf(s[nt][0] - m0);  rs0 += s[nt][0];
            s[nt][1] = __expf(s[nt][1] - m0);  rs0 += s[nt][1];
            s[nt][2] = __expf(s[nt][2] - m1);  rs1 += s[nt][2];
            s[nt][3] = __expf(s[nt][3] - m1);  rs1 += s[nt][3];
        }
#pragma unroll
        for (int off = 1; off < 4; off <<= 1) {
            rs0 += __shfl_xor_sync(0xffffffffu, rs0, off);
            rs1 += __shfl_xor_sync(0xffffffffu, rs1, off);
        }
        l0 = l0 * sc0 + rs0;
        l1 = l1 * sc1 + rs1;
#pragma unroll
        for (int nd = 0; nd < 8; nd++) {
            o[nd][0] *= sc0;  o[nd][1] *= sc0;
            o[nd][2] *= sc1;  o[nd][3] *= sc1;
        }

        // ---- O += P @ V ----
#pragma unroll
        for (int kk = 0; kk < 4; kk++) {
            uint32_t ph[4], pl[4];
            ph[0] = pack2(s[2 * kk][0], s[2 * kk][1]);
            ph[1] = pack2(s[2 * kk][2], s[2 * kk][3]);
            ph[2] = pack2(s[2 * kk + 1][0], s[2 * kk + 1][1]);
            ph[3] = pack2(s[2 * kk + 1][2], s[2 * kk + 1][3]);
            pl[0] = pack2lo(s[2 * kk][0], s[2 * kk][1], ph[0]);
            pl[1] = pack2lo(s[2 * kk][2], s[2 * kk][3], ph[1]);
            pl[2] = pack2lo(s[2 * kk + 1][0], s[2 * kk + 1][1], ph[2]);
            pl[3] = pack2lo(s[2 * kk + 1][2], s[2 * kk + 1][3], ph[3]);
#pragma unroll
            for (int half = 0; half < 2; half++) {
                uint32_t vh[4][2], vl[4][2];
#pragma unroll
                for (int pp = 0; pp < 2; pp++) {
                    int p2 = half * 2 + pp;
                    uint32_t row = kk * 16 + ((lane >> 3) & 1) * 8 + (lane & 7);
                    uint32_t off = (row * SKW + (2 * p2 + ((lane >> 4) & 1)) * 4) * 4;
                    ldsm4t(vh[2*pp][0], vh[2*pp][1], vh[2*pp+1][0], vh[2*pp+1][1], vhB + off);
                    ldsm4t(vl[2*pp][0], vl[2*pp][1], vl[2*pp+1][0], vl[2*pp+1][1], vlB + off);
                }
#pragma unroll
                for (int j = 0; j < 4; j++)
                    mma16816(o[half*4+j], ph, vh[j][0], vh[j][1]);
#pragma unroll
                for (int j = 0; j < 4; j++)
                    mma16816(o[half*4+j], ph, vl[j][0], vl[j][1]);
#pragma unroll
                for (int j = 0; j < 4; j++)
                    mma16816(o[half*4+j], pl, vh[j][0], vh[j][1]);
            }
        }

        // ---- convert + store next tile into the other buffer ----
        if (more) {
            uint32_t* KhN = asm_ + (p ^ 1) * BUF_W;
            uint32_t* KlN = KhN + TILE_W;
            uint32_t* VhN = KlN + TILE_W;
            uint32_t* VlN = VhN + TILE_W;
#pragma unroll
            for (int i = 0; i < 4; i++) {
                int idx = tid + i * 256, r = idx >> 4, q4 = idx & 15;
                uint32_t h0 = pack2(pk[i].x, pk[i].y), h1 = pack2(pk[i].z, pk[i].w);
                KhN[r * SKW + q4 * 2] = h0;  KhN[r * SKW + q4 * 2 + 1] = h1;
                KlN[r * SKW + q4 * 2] = pack2lo(pk[i].x, pk[i].y, h0);
                KlN[r * SKW + q4 * 2 + 1] = pack2lo(pk[i].z, pk[i].w, h1);
                uint32_t w0 = pack2(pv[i].x, pv[i].y), w1 = pack2(pv[i].z, pv[i].w);
                VhN[r * SKW + q4 * 2] = w0;  VhN[r * SKW + q4 * 2 + 1] = w1;
                VlN[r * SKW + q4 * 2] = pack2lo(pv[i].x, pv[i].y, w0);
                VlN[r * SKW + q4 * 2 + 1] = pack2lo(pv[i].z, pv[i].w, w1);
            }
        }
        __syncthreads();
    }

    // ---- epilogue ----
    float inv0 = 1.0f / l0, inv1 = 1.0f / l1;
    float* op = out + qoff + (size_t)qrow * INNER_;
#pragma unroll
    for (int nd = 0; nd < 8; nd++) {
        *(float2*)&op[nd * 8 + 2 * t] =
            make_float2(o[nd][0] * inv0, o[nd][1] * inv0);
        *(float2*)&op[8 * INNER_ + nd * 8 + 2 * t] =
            make_float2(o[nd][2] * inv1, o[nd][3] * inv1);
    }
}

// ---------------- launch ----------------
extern "C" void kernel_launch(void* const* d_in, const int* in_sizes, int n_in,
                              void* d_out, int out_size)
{
    (void)in_sizes; (void)n_in; (void)out_size;
    const float* x    = (const float*)d_in[0];
    const float* y    = (const float*)d_in[1];
    const float* mask = (const float*)d_in[2];
    const float* Wq   = (const float*)d_in[3];
    const float* Wk   = (const float*)d_in[4];
    const float* Wv   = (const float*)d_in[5];
    const float* Wo   = (const float*)d_in[6];
    float* out = (float*)d_out;

    float *q, *k, *v, *ao;
    cudaGetSymbolAddress((void**)&q,  g_q);
    cudaGetSymbolAddress((void**)&k,  g_k);
    cudaGetSymbolAddress((void**)&v,  g_v);
    cudaGetSymbolAddress((void**)&ao, g_ao);

    // projections: [B*L, DIM] @ [INNER, DIM]^T
    dim3 gP(INNER_ / 64, (B_ * LQ_) / 128);
    gemm_tc_kernel<<<gP, 256>>>(x, Wq, q, B_ * LQ_, INNER_, DIM_, 0.125f);
    gemm_tc_kernel<<<gP, 256>>>(y, Wk, k, B_ * LK_, INNER_, DIM_, 1.0f);
    gemm_tc_kernel<<<gP, 256>>>(y, Wv, v, B_ * LK_, INNER_, DIM_, 1.0f);

    // fused masked attention
    cudaFuncSetAttribute(attn_tc_kernel,
                         cudaFuncAttributeMaxDynamicSharedMemorySize, ATTN_SMEM_BYTES);
    attn_tc_kernel<<<dim3(LQ_ / 128, HEADS_, B_), 256, ATTN_SMEM_BYTES>>>(q, k, v, mask, ao);

    // output projection: [B*LQ, INNER] @ [DIM, INNER]^T -> d_out
    gemm_tc_kernel<<<dim3(DIM_ / 64, (B_ * LQ_) / 128), 256>>>(
        ao, Wo, out, B_ * LQ_, DIM_, INNER_, 1.0f);
}

// round 7
// speedup vs baseline: 5.0923x; 1.1920x over previous
#include <cuda_runtime.h>
#include <cuda_bf16.h>
#include <cstring>
#include <cstdint>

#define B_    2
#define LQ_   2048
#define LK_   2048
#define DIM_  1024
#define HEADS_ 8
#define DH_   64
#define INNER_ 512

// ---------------- scratch (static device globals; no allocation) ----------------
__device__ __nv_bfloat16 g_qh[B_ * LQ_ * INNER_];
__device__ __nv_bfloat16 g_ql[B_ * LQ_ * INNER_];
__device__ __nv_bfloat16 g_kh[B_ * LK_ * INNER_];
__device__ __nv_bfloat16 g_kl[B_ * LK_ * INNER_];
__device__ __nv_bfloat16 g_vh[B_ * LK_ * INNER_];
__device__ __nv_bfloat16 g_vl[B_ * LK_ * INNER_];
__device__ float         g_ao[B_ * LQ_ * INNER_];

// ---------------- helpers ----------------
__device__ __forceinline__ uint32_t pack2(float x, float y) {
    __nv_bfloat162 t = __floats2bfloat162_rn(x, y);
    uint32_t r;
    memcpy(&r, &t, 4);
    return r;
}
__device__ __forceinline__ uint32_t pack2lo(float x, float y, uint32_t hi) {
    __nv_bfloat162 h;
    memcpy(&h, &hi, 4);
    return pack2(x - __low2float(h), y - __high2float(h));
}

__device__ __forceinline__ void mma16816(float* c, const uint32_t* a,
                                         uint32_t b0, uint32_t b1) {
    asm volatile(
        "mma.sync.aligned.m16n8k16.row.col.f32.bf16.bf16.f32 "
        "{%0,%1,%2,%3}, {%4,%5,%6,%7}, {%8,%9}, {%0,%1,%2,%3};"
        : "+f"(c[0]), "+f"(c[1]), "+f"(c[2]), "+f"(c[3])
        : "r"(a[0]), "r"(a[1]), "r"(a[2]), "r"(a[3]), "r"(b0), "r"(b1));
}

__device__ __forceinline__ void ldsm4(uint32_t& r0, uint32_t& r1,
                                      uint32_t& r2, uint32_t& r3, uint32_t addr) {
    asm volatile("ldmatrix.sync.aligned.m8n8.x4.shared.b16 {%0,%1,%2,%3}, [%4];"
                 : "=r"(r0), "=r"(r1), "=r"(r2), "=r"(r3) : "r"(addr));
}
__device__ __forceinline__ void ldsm4t(uint32_t& r0, uint32_t& r1,
                                       uint32_t& r2, uint32_t& r3, uint32_t addr) {
    asm volatile("ldmatrix.sync.aligned.m8n8.x4.trans.shared.b16 {%0,%1,%2,%3}, [%4];"
                 : "=r"(r0), "=r"(r1), "=r"(r2), "=r"(r3) : "r"(addr));
}
__device__ __forceinline__ uint32_t sptr(const void* p) {
    return (uint32_t)__cvta_generic_to_shared(p);
}
__device__ __forceinline__ void cpa16(uint32_t saddr, const void* g) {
    asm volatile("cp.async.cg.shared.global [%0], [%1], 16;"
                 :: "r"(saddr), "l"(g) : "memory");
}
__device__ __forceinline__ void cpa_commit() {
    asm volatile("cp.async.commit_group;" ::: "memory");
}
template<int N>
__device__ __forceinline__ void cpa_wait() {
    asm volatile("cp.async.wait_group %0;" :: "n"(N) : "memory");
}

// ---------------- tensor-core GEMM: C[M,N] = alpha * A[M,K] @ W[N,K]^T ----------
// Block tile 128x64, BK=32. 8 warps (4m x 2n). Split-bf16 3-MMA fp32 emulation.
// BF16OUT=1 writes (hi, lo) bf16 pair arrays; BF16OUT=0 writes fp32 C.
template<int BF16OUT>
__global__ __launch_bounds__(256, 2)
void gemm_tc_kernel(const float* __restrict__ A, const float* __restrict__ W,
                    float* __restrict__ Cf,
                    __nv_bfloat16* __restrict__ Ch, __nv_bfloat16* __restrict__ Cl,
                    int M, int N, int K, float alpha)
{
    __shared__ __align__(16) uint32_t Ah[128 * 20], Al[128 * 20];
    __shared__ __align__(16) uint32_t Bh[64 * 20],  Bl[64 * 20];

    const int tid = threadIdx.x;
    const int lane = tid & 31, warp = tid >> 5;
    const int wm = warp & 3, wn = warp >> 2;
    const int g = lane >> 2, t = lane & 3;
    const int bm = blockIdx.y * 128, bn = blockIdx.x * 64;

    const uint32_t ahB = sptr(Ah), alB = sptr(Al), bhB = sptr(Bh), blB = sptr(Bl);

    float c[2][4][4];
#pragma unroll
    for (int mt = 0; mt < 2; mt++)
#pragma unroll
        for (int nt = 0; nt < 4; nt++)
#pragma unroll
            for (int j = 0; j < 4; j++) c[mt][nt][j] = 0.0f;

    float4 pa[4], pb[2];
#pragma unroll
    for (int i = 0; i < 4; i++) {
        int idx = tid + i * 256, m = idx >> 3, q = idx & 7;
        pa[i] = *(const float4*)&A[(size_t)(bm + m) * K + q * 4];
    }
#pragma unroll
    for (int i = 0; i < 2; i++) {
        int idx = tid + i * 256, m = idx >> 3, q = idx & 7;
        pb[i] = *(const float4*)&W[(size_t)(bn + m) * K + q * 4];
    }

    for (int k0 = 32;; k0 += 32) {
#pragma unroll
        for (int i = 0; i < 4; i++) {
            int idx = tid + i * 256, m = idx >> 3, q = idx & 7;
            uint32_t h0 = pack2(pa[i].x, pa[i].y), h1 = pack2(pa[i].z, pa[i].w);
            Ah[m * 20 + q * 2] = h0;  Ah[m * 20 + q * 2 + 1] = h1;
            Al[m * 20 + q * 2] = pack2lo(pa[i].x, pa[i].y, h0);
            Al[m * 20 + q * 2 + 1] = pack2lo(pa[i].z, pa[i].w, h1);
        }
#pragma unroll
        for (int i = 0; i < 2; i++) {
            int idx = tid + i * 256, m = idx >> 3, q = idx & 7;
            uint32_t h0 = pack2(pb[i].x, pb[i].y), h1 = pack2(pb[i].z, pb[i].w);
            Bh[m * 20 + q * 2] = h0;  Bh[m * 20 + q * 2 + 1] = h1;
            Bl[m * 20 + q * 2] = pack2lo(pb[i].x, pb[i].y, h0);
            Bl[m * 20 + q * 2 + 1] = pack2lo(pb[i].z, pb[i].w, h1);
        }
        __syncthreads();

        const bool last = (k0 >= K);
        if (!last) {
#pragma unroll
            for (int i = 0; i < 4; i++) {
                int idx = tid + i * 256, m = idx >> 3, q = idx & 7;
                pa[i] = *(const float4*)&A[(size_t)(bm + m) * K + k0 + q * 4];
            }
#pragma unroll
            for (int i = 0; i < 2; i++) {
                int idx = tid + i * 256, m = idx >> 3, q = idx & 7;
                pb[i] = *(const float4*)&W[(size_t)(bn + m) * K + k0 + q * 4];
            }
        }

#pragma unroll
        for (int s = 0; s < 2; s++) {
            uint32_t ah[2][4], al[2][4];
#pragma unroll
            for (int mt = 0; mt < 2; mt++) {
                uint32_t row = wm * 32 + mt * 16 + (lane & 7) + ((lane >> 3) & 1) * 8;
                uint32_t off = (row * 20 + s * 8 + ((lane >> 4) & 1) * 4) * 4;
                ldsm4(ah[mt][0], ah[mt][1], ah[mt][2], ah[mt][3], ahB + off);
                ldsm4(al[mt][0], al[mt][1], al[mt][2], al[mt][3], alB + off);
            }
            uint32_t bh[4][2], bl[4][2];
#pragma unroll
            for (int p2 = 0; p2 < 2; p2++) {
                uint32_t row = wn * 32 + p2 * 16 + ((lane >> 4) & 1) * 8 + (lane & 7);
                uint32_t off = (row * 20 + s * 8 + ((lane >> 3) & 1) * 4) * 4;
                ldsm4(bh[2*p2][0], bh[2*p2][1], bh[2*p2+1][0], bh[2*p2+1][1], bhB + off);
                ldsm4(bl[2*p2][0], bl[2*p2][1], bl[2*p2+1][0], bl[2*p2+1][1], blB + off);
            }
#pragma unroll
            for (int nt = 0; nt < 4; nt++)
#pragma unroll
                for (int mt = 0; mt < 2; mt++)
                    mma16816(c[mt][nt], ah[mt], bh[nt][0], bh[nt][1]);
#pragma unroll
            for (int nt = 0; nt < 4; nt++)
#pragma unroll
                for (int mt = 0; mt < 2; mt++)
                    mma16816(c[mt][nt], ah[mt], bl[nt][0], bl[nt][1]);
#pragma unroll
            for (int nt = 0; nt < 4; nt++)
#pragma unroll
                for (int mt = 0; mt < 2; mt++)
                    mma16816(c[mt][nt], al[mt], bh[nt][0], bh[nt][1]);
        }
        if (last) break;
        __syncthreads();
    }

    // epilogue
#pragma unroll
    for (int mt = 0; mt < 2; mt++) {
        int row = bm + wm * 32 + mt * 16 + g;
#pragma unroll
        for (int nt = 0; nt < 4; nt++) {
            int col = bn + wn * 32 + nt * 8 + 2 * t;
            float v0 = c[mt][nt][0] * alpha, v1 = c[mt][nt][1] * alpha;
            float v2 = c[mt][nt][2] * alpha, v3 = c[mt][nt][3] * alpha;
            if (BF16OUT) {
                uint32_t h0 = pack2(v0, v1), h1 = pack2(v2, v3);
                *(uint32_t*)&Ch[(size_t)row * N + col] = h0;
                *(uint32_t*)&Cl[(size_t)row * N + col] = pack2lo(v0, v1, h0);
                *(uint32_t*)&Ch[(size_t)(row + 8) * N + col] = h1;
                *(uint32_t*)&Cl[(size_t)(row + 8) * N + col] = pack2lo(v2, v3, h1);
            } else {
                *(float2*)&Cf[(size_t)row * N + col] = make_float2(v0, v1);
                *(float2*)&Cf[(size_t)(row + 8) * N + col] = make_float2(v2, v3);
            }
        }
    }
}

// ---------------- fused masked flash attention v2 ----------------
// Block: 128 q rows x (head, batch); 8 warps, warp w owns rows [16w, 16w+16).
// Inputs already bf16 hi/lo (pre-converted by projection GEMM epilogue).
// Q tile in smem (ldmatrix per use); K/V double-buffered via cp.async.
// All smem tiles: 64 bf16 = 128B rows, XOR-swizzled (o ^= (o>>3)&0x70 pattern
// applied as chunk ^ ((row&7)<<4)) -> conflict-free ldmatrix + cp.async.
// 2 blocks/SM (regs capped at 128) -> 16 warps, grid 256 = one wave.
#define SM_QH 0
#define SM_QL 16384
#define SM_K(p)  (32768 + (p) * 16384)      // hi at +0, lo at +8192
#define SM_V(p)  (65536 + (p) * 16384)
#define ATTN_SMEM_BYTES 98304

__device__ __forceinline__ void stage_kv(uint32_t dst,
                                         const __nv_bfloat16* __restrict__ hsrc,
                                         const __nv_bfloat16* __restrict__ lsrc,
                                         int tid)
{
#pragma unroll
    for (int i = 0; i < 2; i++) {
        int idx = tid + i * 256;            // 0..511 : 64 rows x 8 chunks
        int r = idx >> 3, c = idx & 7;
        uint32_t sw = (uint32_t)((c * 16) ^ ((r & 7) << 4));
        cpa16(dst + r * 128 + sw, hsrc + (size_t)r * INNER_ + c * 8);
        cpa16(dst + 8192 + r * 128 + sw, lsrc + (size_t)r * INNER_ + c * 8);
    }
}

__global__ __launch_bounds__(256, 2)
void attn_tc_kernel(const __nv_bfloat16* __restrict__ qh,
                    const __nv_bfloat16* __restrict__ ql,
                    const __nv_bfloat16* __restrict__ kh,
                    const __nv_bfloat16* __restrict__ kl,
                    const __nv_bfloat16* __restrict__ vh,
                    const __nv_bfloat16* __restrict__ vl,
                    const float* __restrict__ mask,
                    float* __restrict__ out)
{
    extern __shared__ __align__(16) char smem[];
    const uint32_t sbase = sptr(smem);

    const int tid = threadIdx.x;
    const int lane = tid & 31, warp = tid >> 5;
    const int g = lane >> 2, t = lane & 3;
    const int qti = blockIdx.x, h = blockIdx.y, b = blockIdx.z;
    const int qbase = qti * 128;
    const size_t qoff = ((size_t)b * LQ_ + qbase) * INNER_ + h * DH_;
    const int qrow = warp * 16 + g;
    const int NT = LK_ / 64;

    // ---- prologue: cp.async Q tile + K/V tiles 0 and 1 ----
#pragma unroll
    for (int i = 0; i < 8; i++) {
        int idx = tid + i * 256;            // 0..2047
        int arr = idx >> 10;                // 0: hi, 1: lo
        int r = (idx >> 3) & 127, c = idx & 7;
        uint32_t sw = (uint32_t)((c * 16) ^ ((r & 7) << 4));
        const __nv_bfloat16* src = (arr ? ql : qh) + qoff + (size_t)r * INNER_ + c * 8;
        cpa16(sbase + arr * 16384 + r * 128 + sw, src);
    }
    {
        const size_t k0 = ((size_t)b * LK_) * INNER_ + h * DH_;
        stage_kv(sbase + SM_K(0), kh + k0, kl + k0, tid);
        stage_kv(sbase + SM_V(0), vh + k0, vl + k0, tid);
    }
    cpa_commit();                           // G0 = {Q, K0, V0}
    {
        const size_t k1 = ((size_t)b * LK_ + 64) * INNER_ + h * DH_;
        stage_kv(sbase + SM_K(1), kh + k1, kl + k1, tid);
        stage_kv(sbase + SM_V(1), vh + k1, vl + k1, tid);
    }
    cpa_commit();                           // G1 = {K1, V1}
    cpa_wait<1>();                          // G0 complete
    __syncthreads();

    float m0 = -1e30f, m1 = -1e30f, l0 = 0.0f, l1 = 0.0f;
    float o[8][4];
#pragma unroll
    for (int nd = 0; nd < 8; nd++)
#pragma unroll
        for (int j = 0; j < 4; j++) o[nd][j] = 0.0f;

    for (int kt = 0; kt < NT; kt++) {
        const int p = kt & 1;
        const uint32_t sK = sbase + SM_K(p);
        const uint32_t sV = sbase + SM_V(p);

        // ---- S = Q K^T ----
        float s[8][4];
#pragma unroll
        for (int nt = 0; nt < 8; nt++)
#pragma unroll
            for (int j = 0; j < 4; j++) s[nt][j] = 0.0f;

#pragma unroll
        for (int s16 = 0; s16 < 4; s16++) {
            uint32_t qfh[4], qfl[4];
            {
                int row = warp * 16 + (lane & 7) + ((lane >> 3) & 1) * 8;
                uint32_t co = (uint32_t)((s16 * 32 + ((lane >> 4) & 1) * 16)
                                         ^ ((row & 7) << 4));
                uint32_t off = row * 128 + co;
                ldsm4(qfh[0], qfh[1], qfh[2], qfh[3], sbase + SM_QH + off);
                ldsm4(qfl[0], qfl[1], qfl[2], qfl[3], sbase + SM_QL + off);
            }
#pragma unroll
            for (int half = 0; half < 2; half++) {
                uint32_t bh[4][2], bl[4][2];
#pragma unroll
                for (int pp = 0; pp < 2; pp++) {
                    int p2 = half * 2 + pp;
                    int row = p2 * 16 + ((lane >> 4) & 1) * 8 + (lane & 7);
                    uint32_t co = (uint32_t)((s16 * 32 + ((lane >> 3) & 1) * 16)
                                             ^ ((row & 7) << 4));
                    uint32_t off = row * 128 + co;
                    ldsm4(bh[2*pp][0], bh[2*pp][1], bh[2*pp+1][0], bh[2*pp+1][1], sK + off);
                    ldsm4(bl[2*pp][0], bl[2*pp][1], bl[2*pp+1][0], bl[2*pp+1][1], sK + 8192 + off);
                }
#pragma unroll
                for (int j = 0; j < 4; j++)
                    mma16816(s[half*4+j], qfh, bh[j][0], bh[j][1]);
#pragma unroll
                for (int j = 0; j < 4; j++)
                    mma16816(s[half*4+j], qfh, bl[j][0], bl[j][1]);
#pragma unroll
                for (int j = 0; j < 4; j++)
                    mma16816(s[half*4+j], qfl, bh[j][0], bh[j][1]);
            }
        }

        // ---- additive mask ----
        {
            const float* mrow0 = mask + ((size_t)b * LQ_ + qbase + qrow) * LK_ + kt * 64;
            const float* mrow1 = mrow0 + 8 * (size_t)LK_;
#pragma unroll
            for (int nt = 0; nt < 8; nt++) {
                float2 ma = *(const float2*)&mrow0[nt * 8 + 2 * t];
                float2 mb = *(const float2*)&mrow1[nt * 8 + 2 * t];
                s[nt][0] -= ma.x * 1e9f;  s[nt][1] -= ma.y * 1e9f;
                s[nt][2] -= mb.x * 1e9f;  s[nt][3] -= mb.y * 1e9f;
            }
        }

        // ---- online softmax (warp-local; rows g and g+8) ----
        float rm0 = -1e30f, rm1 = -1e30f;
#pragma unroll
        for (int nt = 0; nt < 8; nt++) {
            rm0 = fmaxf(rm0, fmaxf(s[nt][0], s[nt][1]));
            rm1 = fmaxf(rm1, fmaxf(s[nt][2], s[nt][3]));
        }
#pragma unroll
        for (int off = 1; off < 4; off <<= 1) {
            rm0 = fmaxf(rm0, __shfl_xor_sync(0xffffffffu, rm0, off));
            rm1 = fmaxf(rm1, __shfl_xor_sync(0xffffffffu, rm1, off));
        }
        float nm0 = fmaxf(m0, rm0), nm1 = fmaxf(m1, rm1);
        float sc0 = __expf(m0 - nm0), sc1 = __expf(m1 - nm1);
        m0 = nm0; m1 = nm1;

        float rs0 = 0.0f, rs1 = 0.0f;
#pragma unroll
        for (int nt = 0; nt < 8; nt++) {
            s[nt][0] = __expf(s[nt][0] - m0);  rs0 += s[nt][0];
            s[nt][1] = __expf(s[nt][1] - m0);  rs0 += s[nt][1];
            s[nt][2] = __expf(s[nt][2] - m1);  rs1 += s[nt][2];
            s[nt][3] = __expf(s[nt][3] - m1);  rs1 += s[nt][3];
        }
#pragma unroll
        for (int off = 1; off < 4; off <<= 1) {
            rs0 += __shfl_xor_sync(0xffffffffu, rs0, off);
            rs1 += __shfl_xor_sync(0xffffffffu, rs1, off);
        }
        l0 = l0 * sc0 + rs0;
        l1 = l1 * sc1 + rs1;
#pragma unroll
        for (int nd = 0; nd < 8; nd++) {
            o[nd][0] *= sc0;  o[nd][1] *= sc0;
            o[nd][2] *= sc1;  o[nd][3] *= sc1;
        }

        // ---- O += P @ V ----
#pragma unroll
        for (int kk = 0; kk < 4; kk++) {
            uint32_t ph[4], pl[4];
            ph[0] = pack2(s[2 * kk][0], s[2 * kk][1]);
            ph[1] = pack2(s[2 * kk][2], s[2 * kk][3]);
            ph[2] = pack2(s[2 * kk + 1][0], s[2 * kk + 1][1]);
            ph[3] = pack2(s[2 * kk + 1][2], s[2 * kk + 1][3]);
            pl[0] = pack2lo(s[2 * kk][0], s[2 * kk][1], ph[0]);
            pl[1] = pack2lo(s[2 * kk][2], s[2 * kk][3], ph[1]);
            pl[2] = pack2lo(s[2 * kk + 1][0], s[2 * kk + 1][1], ph[2]);
            pl[3] = pack2lo(s[2 * kk + 1][2], s[2 * kk + 1][3], ph[3]);
#pragma unroll
            for (int half = 0; half < 2; half++) {
                uint32_t fh[4][2], fl[4][2];
#pragma unroll
                for (int pp = 0; pp < 2; pp++) {
                    int p2 = half * 2 + pp;
                    int row = kk * 16 + ((lane >> 3) & 1) * 8 + (lane & 7);
                    uint32_t co = (uint32_t)(((2 * p2 + ((lane >> 4) & 1)) * 16)
                                             ^ ((row & 7) << 4));
                    uint32_t off = row * 128 + co;
                    ldsm4t(fh[2*pp][0], fh[2*pp][1], fh[2*pp+1][0], fh[2*pp+1][1], sV + off);
                    ldsm4t(fl[2*pp][0], fl[2*pp][1], fl[2*pp+1][0], fl[2*pp+1][1], sV + 8192 + off);
                }
#pragma unroll
                for (int j = 0; j < 4; j++)
                    mma16816(o[half*4+j], ph, fh[j][0], fh[j][1]);
#pragma unroll
                for (int j = 0; j < 4; j++)
                    mma16816(o[half*4+j], ph, fl[j][0], fl[j][1]);
#pragma unroll
                for (int j = 0; j < 4; j++)
                    mma16816(o[half*4+j], pl, fh[j][0], fh[j][1]);
            }
        }

        // ---- refill stage p with tile kt+2; ensure tile kt+1 resident ----
        if (kt + 1 < NT) {
            __syncthreads();                // all reads of stage p done
            if (kt + 2 < NT) {
                const size_t kn = ((size_t)b * LK_ + (kt + 2) * 64) * INNER_ + h * DH_;
                stage_kv(sbase + SM_K(p), kh + kn, kl + kn, tid);
                stage_kv(sbase + SM_V(p), vh + kn, vl + kn, tid);
                cpa_commit();
                cpa_wait<1>();              // group for kt+1 complete
            } else {
                cpa_wait<0>();
            }
            __syncthreads();
        }
    }

    // ---- epilogue ----
    float inv0 = 1.0f / l0, inv1 = 1.0f / l1;
    float* op = out + qoff + (size_t)qrow * INNER_;
#pragma unroll
    for (int nd = 0; nd < 8; nd++) {
        *(float2*)&op[nd * 8 + 2 * t] =
            make_float2(o[nd][0] * inv0, o[nd][1] * inv0);
        *(float2*)&op[8 * INNER_ + nd * 8 + 2 * t] =
            make_float2(o[nd][2] * inv1, o[nd][3] * inv1);
    }
}

// ---------------- launch ----------------
extern "C" void kernel_launch(void* const* d_in, const int* in_sizes, int n_in,
                              void* d_out, int out_size)
{
    (void)in_sizes; (void)n_in; (void)out_size;
    const float* x    = (const float*)d_in[0];
    const float* y    = (const float*)d_in[1];
    const float* mask = (const float*)d_in[2];
    const float* Wq   = (const float*)d_in[3];
    const float* Wk   = (const float*)d_in[4];
    const float* Wv   = (const float*)d_in[5];
    const float* Wo   = (const float*)d_in[6];
    float* out = (float*)d_out;

    __nv_bfloat16 *qh, *ql, *kh, *kl, *vh, *vl;
    float* ao;
    cudaGetSymbolAddress((void**)&qh, g_qh);
    cudaGetSymbolAddress((void**)&ql, g_ql);
    cudaGetSymbolAddress((void**)&kh, g_kh);
    cudaGetSymbolAddress((void**)&kl, g_kl);
    cudaGetSymbolAddress((void**)&vh, g_vh);
    cudaGetSymbolAddress((void**)&vl, g_vl);
    cudaGetSymbolAddress((void**)&ao, g_ao);

    // projections -> bf16 hi/lo pairs (scale folded into Q)
    dim3 gP(INNER_ / 64, (B_ * LQ_) / 128);
    gemm_tc_kernel<1><<<gP, 256>>>(x, Wq, nullptr, qh, ql, B_ * LQ_, INNER_, DIM_, 0.125f);
    gemm_tc_kernel<1><<<gP, 256>>>(y, Wk, nullptr, kh, kl, B_ * LK_, INNER_, DIM_, 1.0f);
    gemm_tc_kernel<1><<<gP, 256>>>(y, Wv, nullptr, vh, vl, B_ * LK_, INNER_, DIM_, 1.0f);

    // fused masked attention
    cudaFuncSetAttribute(attn_tc_kernel,
                         cudaFuncAttributeMaxDynamicSharedMemorySize, ATTN_SMEM_BYTES);
    attn_tc_kernel<<<dim3(LQ_ / 128, HEADS_, B_), 256, ATTN_SMEM_BYTES>>>(
        qh, ql, kh, kl, vh, vl, mask, ao);

    // output projection -> fp32 d_out
    gemm_tc_kernel<0><<<dim3(DIM_ / 64, (B_ * LQ_) / 128), 256>>>(
        ao, Wo, out, nullptr, nullptr, B_ * LQ_, DIM_, INNER_, 1.0f);
}